// round 9
// baseline (speedup 1.0000x reference)
#include <cuda_runtime.h>
#include <cstdint>
#include <math.h>

// Problem shape (fixed by the dataset)
constexpr int B_  = 8;
constexpr int N_  = 2048;
constexpr int M_  = 2048;
constexpr int C_  = 512;

// -------- scratch (device-global arrays: allocation-free rule) --------
__device__ float g_S [(size_t)B_ * N_ * M_];   // scores, then probabilities (in-place)
__device__ float g_Vt[(size_t)B_ * C_ * M_];   // V^T per batch [C][M] (tf32-rounded)
__device__ float g_G [(size_t)B_ * N_ * C_];   // gated activations (tf32-rounded)
__device__ float g_H [(size_t)B_ * N_ * C_];   // MLP hidden (tf32-rounded)
__device__ float g_Wt[3 * C_ * C_];            // Wv^T, W1^T, W2^T (tf32-rounded)
__device__ float g_Dr[(size_t)B_ * N_ * C_];   // dec, tf32-rounded
__device__ float g_Er[(size_t)B_ * M_ * C_];   // enc, tf32-rounded

// fp32 -> tf32 round-to-nearest (HW truncation of low 13 bits completes RN)
__device__ __forceinline__ float rnd(float f) {
    return __uint_as_float(__float_as_uint(f) + 0x1000u);
}

__device__ __forceinline__ void cp16(void* smem, const void* gmem) {
    unsigned sa = (unsigned)__cvta_generic_to_shared(smem);
    asm volatile("cp.async.cg.shared.global [%0], [%1], 16;\n" :: "r"(sa), "l"(gmem));
}
#define CP_COMMIT() asm volatile("cp.async.commit_group;\n")
#define CP_WAIT2()  asm volatile("cp.async.wait_group 2;\n")

// ==================== small prep kernels ====================
__global__ void round_copy4(const float4* __restrict__ in, float4* __restrict__ out, int n4) {
    int i = blockIdx.x * 256 + threadIdx.x;
    if (i < n4) {
        float4 v = in[i];
        v.x = rnd(v.x); v.y = rnd(v.y); v.z = rnd(v.z); v.w = rnd(v.w);
        out[i] = v;
    }
}

__global__ void transpose512(const float* __restrict__ in, float* __restrict__ out) {
    __shared__ float tile[32][33];
    int x = blockIdx.x * 32 + threadIdx.x;
    int y = blockIdx.y * 32 + threadIdx.y;
#pragma unroll
    for (int i = 0; i < 32; i += 8)
        tile[threadIdx.y + i][threadIdx.x] = in[(size_t)(y + i) * C_ + x];
    __syncthreads();
    int x2 = blockIdx.y * 32 + threadIdx.x;
    int y2 = blockIdx.x * 32 + threadIdx.y;
#pragma unroll
    for (int i = 0; i < 32; i += 8)
        out[(size_t)(y2 + i) * C_ + x2] = rnd(tile[threadIdx.x][threadIdx.y + i]);
}

// ==================== legacy-MMA tf32 NT GEMM ====================
// D[i,j] = sum_k A[i,k]*B[j,k].  CTA tile 128(M) x 256(N), K in 32-chunks.
// 8 warps, each owning a 64x64 sub-tile (2x4 warp grid). 4-stage cp.async.
// EPI: 0=rnd(v+bias[row]) 1=v*extra 2=rnd(extra*(1+tanh(v))) 3=rnd(relu(v+bias[col])) 4=v+bias[col]
#define MMA_TF32(d, a, b)                                                      \
    asm volatile(                                                              \
        "mma.sync.aligned.m16n8k8.row.col.f32.tf32.tf32.f32 "                  \
        "{%0,%1,%2,%3}, {%4,%5,%6,%7}, {%8,%9}, {%0,%1,%2,%3};\n"              \
        : "+f"(d[0]), "+f"(d[1]), "+f"(d[2]), "+f"(d[3])                       \
        : "r"(a[0]), "r"(a[1]), "r"(a[2]), "r"(a[3]), "r"(b[0]), "r"(b[1]))

constexpr int STAGES  = 4;
constexpr int STAGE_F = (128 + 256) * 32;            // floats per stage (sA+sB) = 48KB
constexpr int GEMM_SMEM = STAGES * STAGE_F * 4;      // 192 KB

template <int EPI>
__global__ __launch_bounds__(256, 1)
void gemm_nt(const float* __restrict__ A, const float* __restrict__ Bop,
             float* __restrict__ D, const float* __restrict__ bias,
             const float* __restrict__ extra,
             int Ncols, int K,
             size_t batA, size_t batB, size_t batD, size_t batE) {
    extern __shared__ float smem[];

    const int tid  = threadIdx.x;
    const int warp = tid >> 5, lane = tid & 31;
    const int wm = warp >> 2, wn = warp & 3;      // 2 x 4 warps, each 64x64
    const int g = lane >> 2, t = lane & 3;

    const float* Ag = A   + (size_t)blockIdx.z * batA + (size_t)blockIdx.y * 128 * K;
    const float* Bg = Bop + (size_t)blockIdx.z * batB + (size_t)blockIdx.x * 256 * K;

    // loader mapping: thread tid loads B row tid; threads <128 also load A row tid.
    const int swzB = ((tid & 7) << 2);

    auto issue = [&](int kt, int stg) {
        float* sA = smem + stg * STAGE_F;
        float* sB = sA + 128 * 32;
        const float* b0 = Bg + (size_t)kt * 32 + (size_t)tid * K;
        float* bdst = sB + tid * 32;
#pragma unroll
        for (int c = 0; c < 8; ++c)
            cp16(bdst + ((c << 2) ^ swzB), b0 + c * 4);
        if (tid < 128) {
            const float* a0 = Ag + (size_t)kt * 32 + (size_t)tid * K;
            float* adst = sA + tid * 32;
#pragma unroll
            for (int c = 0; c < 8; ++c)
                cp16(adst + ((c << 2) ^ swzB), a0 + c * 4);
        }
    };

    float acc[4][8][4];
#pragma unroll
    for (int a = 0; a < 4; ++a)
#pragma unroll
        for (int b = 0; b < 8; ++b)
#pragma unroll
            for (int r = 0; r < 4; ++r) acc[a][b][r] = 0.f;

    const int nkt = K >> 5;                      // >= 16 always
    issue(0, 0); CP_COMMIT();
    issue(1, 1); CP_COMMIT();
    issue(2, 2); CP_COMMIT();

    const int sw = g << 2;                       // fragment row & 7 == g for all rows used

#pragma unroll 1
    for (int kt = 0; kt < nkt; ++kt) {
        CP_WAIT2();                              // stage kt landed (2 groups still pending)
        __syncthreads();
        if (kt + 3 < nkt) issue(kt + 3, (kt + 3) & (STAGES - 1));
        CP_COMMIT();                             // keep group count uniform

        const float* sA = smem + (kt & (STAGES - 1)) * STAGE_F;
        const float* sB = sA + 128 * 32;

#pragma unroll
        for (int ks = 0; ks < 4; ++ks) {
            const int kc = ks * 8 + t;
            const int c0 = kc ^ sw, c1 = (kc + 4) ^ sw;
            unsigned af[4][4], bf[8][2];
#pragma unroll
            for (int am = 0; am < 4; ++am) {
                const float* base = sA + (wm * 64 + am * 16 + g) * 32;
                af[am][0] = __float_as_uint(base[c0]);
                af[am][1] = __float_as_uint(base[8 * 32 + c0]);
                af[am][2] = __float_as_uint(base[c1]);
                af[am][3] = __float_as_uint(base[8 * 32 + c1]);
            }
#pragma unroll
            for (int an = 0; an < 8; ++an) {
                const float* nb = sB + (wn * 64 + an * 8 + g) * 32;
                bf[an][0] = __float_as_uint(nb[c0]);
                bf[an][1] = __float_as_uint(nb[c1]);
            }
#pragma unroll
            for (int am = 0; am < 4; ++am)
#pragma unroll
                for (int an = 0; an < 8; ++an)
                    MMA_TF32(acc[am][an], af[am], bf[an]);
        }
    }

    // -------- epilogue --------
    const int mbase = blockIdx.y * 128 + wm * 64;
    const int nbase = blockIdx.x * 256 + wn * 64;
    float* Db = D + (size_t)blockIdx.z * batD;
    const float* Eb = (EPI == 1 || EPI == 2) ? extra + (size_t)blockIdx.z * batE : nullptr;

#pragma unroll
    for (int am = 0; am < 4; ++am) {
#pragma unroll
        for (int half = 0; half < 2; ++half) {
            const int row = mbase + am * 16 + g + half * 8;
            float* drow = Db + (size_t)row * Ncols + nbase + t * 2;
            const float* erow = (EPI == 1 || EPI == 2)
                                ? Eb + (size_t)row * Ncols + nbase + t * 2 : nullptr;
            const float brow = (EPI == 0) ? bias[row] : 0.0f;
#pragma unroll
            for (int an = 0; an < 8; ++an) {
                float v0 = acc[am][an][half * 2 + 0];
                float v1 = acc[am][an][half * 2 + 1];
                const int coff = an * 8;
                float2 o;
                if constexpr (EPI == 0) {
                    o.x = rnd(v0 + brow); o.y = rnd(v1 + brow);
                } else if constexpr (EPI == 1) {
                    float2 e = *reinterpret_cast<const float2*>(erow + coff);
                    o.x = v0 * e.x; o.y = v1 * e.y;
                } else if constexpr (EPI == 2) {
                    float2 e = *reinterpret_cast<const float2*>(erow + coff);
                    o.x = rnd(e.x * (1.0f + tanhf(v0)));
                    o.y = rnd(e.y * (1.0f + tanhf(v1)));
                } else if constexpr (EPI == 3) {
                    const int c = nbase + t * 2 + coff;
                    o.x = rnd(fmaxf(v0 + bias[c], 0.0f));
                    o.y = rnd(fmaxf(v1 + bias[c + 1], 0.0f));
                } else {
                    const int c = nbase + t * 2 + coff;
                    o.x = v0 + bias[c]; o.y = v1 + bias[c + 1];
                }
                *reinterpret_cast<float2*>(drow + coff) = o;
            }
        }
    }
}

// ==================== nonstandard masked softmax ====================
// max over ALL entries; denom includes exp(0-max) for masked entries;
// entries that are exactly 0 stay 0. Output tf32-rounded (feeds PV MMA).
__global__ __launch_bounds__(256)
void softmax_k(float* __restrict__ S) {
    __shared__ float red[8];
    const int tid = threadIdx.x;
    float4* p4 = reinterpret_cast<float4*>(S + (size_t)blockIdx.x * M_);

    float mx = -3.402823466e38f;
    float4 v[2];
#pragma unroll
    for (int j = 0; j < 2; ++j) {
        v[j] = p4[tid + j * 256];
        mx = fmaxf(mx, fmaxf(fmaxf(v[j].x, v[j].y), fmaxf(v[j].z, v[j].w)));
    }
#pragma unroll
    for (int o = 16; o > 0; o >>= 1) mx = fmaxf(mx, __shfl_xor_sync(0xffffffffu, mx, o));
    if ((tid & 31) == 0) red[tid >> 5] = mx;
    __syncthreads();
    if (tid == 0) {
        float m = red[0];
#pragma unroll
        for (int j = 1; j < 8; ++j) m = fmaxf(m, red[j]);
        red[0] = m;
    }
    __syncthreads();
    mx = red[0];
    __syncthreads();

    // exponentiate once, keep e-values; zero-flag via original value
    float e[8];
    float s = 0.f;
#pragma unroll
    for (int j = 0; j < 2; ++j) {
        e[j * 4 + 0] = expf(v[j].x - mx);
        e[j * 4 + 1] = expf(v[j].y - mx);
        e[j * 4 + 2] = expf(v[j].z - mx);
        e[j * 4 + 3] = expf(v[j].w - mx);
        s += e[j * 4 + 0] + e[j * 4 + 1] + e[j * 4 + 2] + e[j * 4 + 3];
    }
#pragma unroll
    for (int o = 16; o > 0; o >>= 1) s += __shfl_xor_sync(0xffffffffu, s, o);
    if ((tid & 31) == 0) red[tid >> 5] = s;
    __syncthreads();
    if (tid == 0) {
        float tot = 0.f;
#pragma unroll
        for (int j = 0; j < 8; ++j) tot += red[j];
        red[0] = tot;
    }
    __syncthreads();
    const float inv = 1.0f / red[0];

#pragma unroll
    for (int j = 0; j < 2; ++j) {
        float4 w;
        w.x = (v[j].x != 0.0f) ? rnd(e[j * 4 + 0] * inv) : 0.0f;
        w.y = (v[j].y != 0.0f) ? rnd(e[j * 4 + 1] * inv) : 0.0f;
        w.z = (v[j].z != 0.0f) ? rnd(e[j * 4 + 2] * inv) : 0.0f;
        w.w = (v[j].w != 0.0f) ? rnd(e[j * 4 + 3] * inv) : 0.0f;
        p4[tid + j * 256] = w;
    }
}

template <int EPI>
static void launch_gemm(dim3 grid, const float* A, const float* Bop, float* D,
                        const float* bias, const float* extra,
                        int Ncols, int K, size_t batA, size_t batB, size_t batD, size_t batE) {
    static bool attr_done = false;
    if (!attr_done) {
        cudaFuncSetAttribute(gemm_nt<EPI>, cudaFuncAttributeMaxDynamicSharedMemorySize, GEMM_SMEM);
        attr_done = true;
    }
    gemm_nt<EPI><<<grid, 256, GEMM_SMEM>>>(A, Bop, D, bias, extra, Ncols, K, batA, batB, batD, batE);
}

extern "C" void kernel_launch(void* const* d_in, const int* in_sizes, int n_in,
                              void* d_out, int out_size) {
    (void)in_sizes; (void)n_in; (void)out_size;
    const float* dec   = (const float*)d_in[0];
    const float* enc   = (const float*)d_in[1];
    const float* trans = (const float*)d_in[2];
    const float* Wv    = (const float*)d_in[3];
    const float* bv    = (const float*)d_in[4];
    const float* W1    = (const float*)d_in[5];
    const float* b1    = (const float*)d_in[6];
    const float* W2    = (const float*)d_in[7];
    const float* b2    = (const float*)d_in[8];
    float* out = (float*)d_out;

    float *S, *Vt, *G, *H, *Wt, *Dr, *Er;
    cudaGetSymbolAddress((void**)&S,  g_S);
    cudaGetSymbolAddress((void**)&Vt, g_Vt);
    cudaGetSymbolAddress((void**)&G,  g_G);
    cudaGetSymbolAddress((void**)&H,  g_H);
    cudaGetSymbolAddress((void**)&Wt, g_Wt);
    cudaGetSymbolAddress((void**)&Dr, g_Dr);
    cudaGetSymbolAddress((void**)&Er, g_Er);
    float* Wvt = Wt;
    float* W1t = Wt + (size_t)C_ * C_;
    float* W2t = Wt + 2 * (size_t)C_ * C_;

    const size_t NC = (size_t)N_ * C_;
    const size_t MC = (size_t)M_ * C_;
    const size_t NM = (size_t)N_ * M_;
    const size_t CM = (size_t)C_ * M_;

    const int n4 = (int)(NC * B_ / 4);
    round_copy4<<<(n4 + 255) / 256, 256>>>((const float4*)dec, (float4*)Dr, n4);
    round_copy4<<<(n4 + 255) / 256, 256>>>((const float4*)enc, (float4*)Er, n4);

    dim3 tb(32, 8), tg(C_ / 32, C_ / 32);
    transpose512<<<tg, tb>>>(Wv, Wvt);
    transpose512<<<tg, tb>>>(W1, W1t);
    transpose512<<<tg, tb>>>(W2, W2t);

    // Vt[b][c][m] = sum_k Wv[k,c]*enc[b,m,k] + bv[c]
    launch_gemm<0>(dim3(M_ / 256, C_ / 128, B_), Wvt, Er, Vt, bv, nullptr, M_, C_, 0, MC, CM, 0);

    // S[b,n,m] = (dec[b,n,:] . enc[b,m,:]) * trans[b,n,m]
    launch_gemm<1>(dim3(M_ / 256, N_ / 128, B_), Dr, Er, S, nullptr, trans, M_, C_, NC, MC, NM, NM);

    // in-place masked softmax over m (writes tf32-rounded P)
    softmax_k<<<B_ * N_, 256>>>(S);

    // G[b,n,c] = dec[b,n,c] * (1 + tanh(sum_m P[b,n,m]*Vt[b][c][m]))
    launch_gemm<2>(dim3(C_ / 256, N_ / 128, B_), S, Vt, G, nullptr, dec, C_, M_, NM, CM, NC, NC);

    // H = relu(G @ W1 + b1)
    launch_gemm<3>(dim3(C_ / 256, (B_ * N_) / 128, 1), G, W1t, H, b1, nullptr, C_, C_, 0, 0, 0, 0);

    // out = H @ W2 + b2
    launch_gemm<4>(dim3(C_ / 256, (B_ * N_) / 128, 1), H, W2t, out, b2, nullptr, C_, C_, 0, 0, 0, 0);
}

// round 11
// speedup vs baseline: 1.3442x; 1.3442x over previous
#include <cuda_runtime.h>
#include <cstdint>
#include <math.h>

// Problem shape (fixed by the dataset)
constexpr int B_  = 8;
constexpr int N_  = 2048;
constexpr int M_  = 2048;
constexpr int C_  = 512;

// -------- scratch (device-global arrays: allocation-free rule) --------
// All GEMM k-operand matrices are stored with each 8-wide k-group permuted by
// P(k) = ((k&3)<<1) | ((k>>2)&1)  so that fragment cols (t, t+4) are adjacent
// in smem and load as one ld.shared.v2.
__device__ float g_S [(size_t)B_ * N_ * M_];   // scores -> probs (in-place, k-perm along M)
__device__ float g_Vt[(size_t)B_ * C_ * M_];   // V^T per batch [C][M] (k-perm along M)
__device__ float g_G [(size_t)B_ * N_ * C_];   // gated activations (k-perm along C)
__device__ float g_H [(size_t)B_ * N_ * C_];   // MLP hidden (k-perm along C)
__device__ float g_Wt[3 * C_ * C_];            // Wv^T, W1^T, W2^T (k-perm along C)
__device__ float g_Dr[(size_t)B_ * N_ * C_];   // dec (k-perm along C)
__device__ float g_Er[(size_t)B_ * M_ * C_];   // enc (k-perm along C)

// fp32 -> tf32 round-to-nearest (HW truncation of low 13 bits completes RN)
__device__ __forceinline__ float rnd(float f) {
    return __uint_as_float(__float_as_uint(f) + 0x1000u);
}

__device__ __forceinline__ void cp16(void* smem, const void* gmem) {
    unsigned sa = (unsigned)__cvta_generic_to_shared(smem);
    asm volatile("cp.async.cg.shared.global [%0], [%1], 16;\n" :: "r"(sa), "l"(gmem));
}
#define CP_COMMIT() asm volatile("cp.async.commit_group;\n")
#define CP_WAIT1()  asm volatile("cp.async.wait_group 1;\n")

// ==================== prep kernels ====================
// rnd + within-8 k-permute: out positions (0..7) = in (0,4,1,5,2,6,3,7)
__global__ void round_perm8(const float4* __restrict__ in, float4* __restrict__ out, int n8) {
    int i = blockIdx.x * 256 + threadIdx.x;     // one thread = 8 floats
    if (i < n8) {
        float4 a = in[2 * i], b = in[2 * i + 1];
        out[2 * i]     = make_float4(rnd(a.x), rnd(b.x), rnd(a.y), rnd(b.y));
        out[2 * i + 1] = make_float4(rnd(a.z), rnd(b.z), rnd(a.w), rnd(b.w));
    }
}

// transpose 512x512 with rnd + k-permute on the output column (k dim)
__global__ void transpose512(const float* __restrict__ in, float* __restrict__ out) {
    __shared__ float tile[32][33];
    int x = blockIdx.x * 32 + threadIdx.x;
    int y = blockIdx.y * 32 + threadIdx.y;
#pragma unroll
    for (int i = 0; i < 32; i += 8)
        tile[threadIdx.y + i][threadIdx.x] = in[(size_t)(y + i) * C_ + x];
    __syncthreads();
    int x2 = blockIdx.y * 32 + threadIdx.x;
    int x2p = (x2 & ~7) | (((x2 & 3) << 1) | ((x2 >> 2) & 1));
    int y2 = blockIdx.x * 32 + threadIdx.y;
#pragma unroll
    for (int i = 0; i < 32; i += 8)
        out[(size_t)(y2 + i) * C_ + x2p] = rnd(tile[threadIdx.x][threadIdx.y + i]);
}

// ==================== legacy-MMA tf32 NT GEMM ====================
// D[i,j] = sum_k A[i,k]*B[j,k].  CTA tile 128x128, K in 32-chunks (k-permuted
// operands), 8 warps at 64x32, 3-stage cp.async, 2 CTAs/SM.
// EPI: 0=rnd(v+bias[row])  [perm store]     1=v*extra            [perm store]
//      2=rnd(extra*(1+tanh(v))) [perm]      3=rnd(relu(v+bias[col])) [perm]
//      4=v+bias[col]       [true store, final output]
#define MMA_TF32(d, a, b)                                                      \
    asm volatile(                                                              \
        "mma.sync.aligned.m16n8k8.row.col.f32.tf32.tf32.f32 "                  \
        "{%0,%1,%2,%3}, {%4,%5,%6,%7}, {%8,%9}, {%0,%1,%2,%3};\n"              \
        : "+f"(d[0]), "+f"(d[1]), "+f"(d[2]), "+f"(d[3])                       \
        : "r"(a[0]), "r"(a[1]), "r"(a[2]), "r"(a[3]), "r"(b[0]), "r"(b[1]))

constexpr int STAGES = 3;
constexpr int STAGE_F = 2 * 128 * 32;              // floats per stage (sA+sB)
constexpr int GEMM_SMEM = STAGES * STAGE_F * 4;    // 96 KB

template <int EPI>
__global__ __launch_bounds__(256, 2)
void gemm_nt(const float* __restrict__ A, const float* __restrict__ Bop,
             float* __restrict__ D, const float* __restrict__ bias,
             const float* __restrict__ extra,
             int Ncols, int K,
             size_t batA, size_t batB, size_t batD, size_t batE) {
    extern __shared__ float smem[];

    const int tid  = threadIdx.x;
    const int warp = tid >> 5, lane = tid & 31;
    const int wm = warp >> 2, wn = warp & 3;       // 2 x 4 warps, each 64x32
    const int g = lane >> 2, t = lane & 3;

    const float* Ag = A   + (size_t)blockIdx.z * batA + (size_t)blockIdx.y * 128 * K;
    const float* Bg = Bop + (size_t)blockIdx.z * batB + (size_t)blockIdx.x * 128 * K;

    const int lrow = tid >> 3;           // 0..31
    const int lcol = (tid & 7) << 2;     // 0,4,...,28
    const int swz  = lcol ^ ((lrow & 7) << 2);

    auto issue = [&](int kb, int stg) {
        float* sA = smem + stg * STAGE_F;
        float* sB = sA + 128 * 32;
        const float* a0 = Ag + kb * 32 + lcol;
        const float* b0 = Bg + kb * 32 + lcol;
#pragma unroll
        for (int i = 0; i < 4; ++i) {
            const int r = lrow + 32 * i;
            cp16(&sA[r * 32 + swz], a0 + (size_t)r * K);
            cp16(&sB[r * 32 + swz], b0 + (size_t)r * K);
        }
    };

    float acc[4][4][4];
#pragma unroll
    for (int a = 0; a < 4; ++a)
#pragma unroll
        for (int b = 0; b < 4; ++b)
#pragma unroll
            for (int r = 0; r < 4; ++r) acc[a][b][r] = 0.f;

    const int nkb = K >> 5;              // >= 16 always
    issue(0, 0); CP_COMMIT();
    issue(1, 1); CP_COMMIT();

    const int sw = g << 2;               // fragment rows all have row&7 == g

    for (int kb = 0; kb < nkb; ++kb) {
        CP_WAIT1();                      // stage kb landed
        __syncthreads();
        if (kb + 2 < nkb) issue(kb + 2, (kb + 2) % STAGES);
        CP_COMMIT();                     // keep group count uniform

        const float* sA = smem + (kb % STAGES) * STAGE_F;
        const float* sB = sA + 128 * 32;

#pragma unroll
        for (int ks = 0; ks < 4; ++ks) {
            // permuted pair (true cols ks*8+t, ks*8+t+4) sits at 2-float offset:
            const int c01 = (ks * 8 + 2 * t) ^ sw;
            unsigned af[4][4], bf[4][2];
#pragma unroll
            for (int am = 0; am < 4; ++am) {
                const float* base = sA + (wm * 64 + am * 16 + g) * 32;
                float2 lo = *reinterpret_cast<const float2*>(base + c01);
                float2 hi = *reinterpret_cast<const float2*>(base + 8 * 32 + c01);
                af[am][0] = __float_as_uint(lo.x);
                af[am][1] = __float_as_uint(hi.x);
                af[am][2] = __float_as_uint(lo.y);
                af[am][3] = __float_as_uint(hi.y);
            }
#pragma unroll
            for (int an = 0; an < 4; ++an) {
                const float* nb = sB + (wn * 32 + an * 8 + g) * 32;
                float2 bv = *reinterpret_cast<const float2*>(nb + c01);
                bf[an][0] = __float_as_uint(bv.x);
                bf[an][1] = __float_as_uint(bv.y);
            }
#pragma unroll
            for (int am = 0; am < 4; ++am)
#pragma unroll
                for (int an = 0; an < 4; ++an)
                    MMA_TF32(acc[am][an], af[am], bf[an]);
        }
    }

    // -------- epilogue --------
    const int mbase = blockIdx.y * 128 + wm * 64;
    const int nbase = blockIdx.x * 128 + wn * 32;
    float* Db = D + (size_t)blockIdx.z * batD;
    const float* Eb = (EPI == 1 || EPI == 2) ? extra + (size_t)blockIdx.z * batE : nullptr;
    // permuted store offsets for this thread's true-col pair (2t, 2t+1):
    // po0 = P(2t) in {0,4,1,5}; partner lands at po0+2.
    const int po0 = ((2 * t) & 3) * 2 + ((2 * t) >> 2);

#pragma unroll
    for (int am = 0; am < 4; ++am) {
#pragma unroll
        for (int half = 0; half < 2; ++half) {
            const int row = mbase + am * 16 + g + half * 8;
            float* drow = Db + (size_t)row * Ncols + nbase;
            const float* erow = (EPI == 1 || EPI == 2) ? Eb + (size_t)row * Ncols + nbase : nullptr;
            const float brow = (EPI == 0) ? bias[row] : 0.0f;
#pragma unroll
            for (int an = 0; an < 4; ++an) {
                float v0 = acc[am][an][half * 2 + 0];
                float v1 = acc[am][an][half * 2 + 1];
                const int coff = an * 8;             // group base (true & permuted agree)
                const int ctru = coff + t * 2;       // true col offset of v0 (v1 = +1)
                float o0, o1;
                if constexpr (EPI == 0) {
                    o0 = rnd(v0 + brow); o1 = rnd(v1 + brow);
                } else if constexpr (EPI == 1) {
                    float2 e = *reinterpret_cast<const float2*>(erow + ctru);
                    o0 = v0 * e.x; o1 = v1 * e.y;
                } else if constexpr (EPI == 2) {
                    float2 e = *reinterpret_cast<const float2*>(erow + ctru);
                    o0 = rnd(e.x * (1.0f + tanhf(v0)));
                    o1 = rnd(e.y * (1.0f + tanhf(v1)));
                } else if constexpr (EPI == 3) {
                    const int c = nbase + ctru;
                    o0 = rnd(fmaxf(v0 + bias[c], 0.0f));
                    o1 = rnd(fmaxf(v1 + bias[c + 1], 0.0f));
                } else {
                    const int c = nbase + ctru;
                    o0 = v0 + bias[c]; o1 = v1 + bias[c + 1];
                }
                if constexpr (EPI == 4) {
                    *reinterpret_cast<float2*>(drow + ctru) = make_float2(o0, o1);
                } else {
                    drow[coff + po0]     = o0;       // k-permuted store
                    drow[coff + po0 + 2] = o1;
                }
            }
        }
    }
}

// ==================== nonstandard masked softmax ====================
// Rows are k-permuted (within-8) — transparent to max/sum/rezero (elementwise).
// max over ALL entries; denom includes exp(0-max) for masked entries;
// entries that are exactly 0 stay 0. Output tf32-rounded (feeds PV MMA).
__global__ __launch_bounds__(256)
void softmax_k(float* __restrict__ S) {
    __shared__ float red[8];
    const int tid = threadIdx.x;
    float4* p4 = reinterpret_cast<float4*>(S + (size_t)blockIdx.x * M_);

    float mx = -3.402823466e38f;
    float4 v[2];
#pragma unroll
    for (int j = 0; j < 2; ++j) {
        v[j] = p4[tid + j * 256];
        mx = fmaxf(mx, fmaxf(fmaxf(v[j].x, v[j].y), fmaxf(v[j].z, v[j].w)));
    }
#pragma unroll
    for (int o = 16; o > 0; o >>= 1) mx = fmaxf(mx, __shfl_xor_sync(0xffffffffu, mx, o));
    if ((tid & 31) == 0) red[tid >> 5] = mx;
    __syncthreads();
    if (tid == 0) {
        float m = red[0];
#pragma unroll
        for (int j = 1; j < 8; ++j) m = fmaxf(m, red[j]);
        red[0] = m;
    }
    __syncthreads();
    mx = red[0];
    __syncthreads();

    float e[8];
    float s = 0.f;
#pragma unroll
    for (int j = 0; j < 2; ++j) {
        e[j * 4 + 0] = expf(v[j].x - mx);
        e[j * 4 + 1] = expf(v[j].y - mx);
        e[j * 4 + 2] = expf(v[j].z - mx);
        e[j * 4 + 3] = expf(v[j].w - mx);
        s += e[j * 4 + 0] + e[j * 4 + 1] + e[j * 4 + 2] + e[j * 4 + 3];
    }
#pragma unroll
    for (int o = 16; o > 0; o >>= 1) s += __shfl_xor_sync(0xffffffffu, s, o);
    if ((tid & 31) == 0) red[tid >> 5] = s;
    __syncthreads();
    if (tid == 0) {
        float tot = 0.f;
#pragma unroll
        for (int j = 0; j < 8; ++j) tot += red[j];
        red[0] = tot;
    }
    __syncthreads();
    const float inv = 1.0f / red[0];

#pragma unroll
    for (int j = 0; j < 2; ++j) {
        float4 w;
        w.x = (v[j].x != 0.0f) ? rnd(e[j * 4 + 0] * inv) : 0.0f;
        w.y = (v[j].y != 0.0f) ? rnd(e[j * 4 + 1] * inv) : 0.0f;
        w.z = (v[j].z != 0.0f) ? rnd(e[j * 4 + 2] * inv) : 0.0f;
        w.w = (v[j].w != 0.0f) ? rnd(e[j * 4 + 3] * inv) : 0.0f;
        p4[tid + j * 256] = w;
    }
}

template <int EPI>
static void launch_gemm(dim3 grid, const float* A, const float* Bop, float* D,
                        const float* bias, const float* extra,
                        int Ncols, int K, size_t batA, size_t batB, size_t batD, size_t batE) {
    static bool attr_done = false;
    if (!attr_done) {
        cudaFuncSetAttribute(gemm_nt<EPI>, cudaFuncAttributeMaxDynamicSharedMemorySize, GEMM_SMEM);
        attr_done = true;
    }
    gemm_nt<EPI><<<grid, 256, GEMM_SMEM>>>(A, Bop, D, bias, extra, Ncols, K, batA, batB, batD, batE);
}

extern "C" void kernel_launch(void* const* d_in, const int* in_sizes, int n_in,
                              void* d_out, int out_size) {
    (void)in_sizes; (void)n_in; (void)out_size;
    const float* dec   = (const float*)d_in[0];
    const float* enc   = (const float*)d_in[1];
    const float* trans = (const float*)d_in[2];
    const float* Wv    = (const float*)d_in[3];
    const float* bv    = (const float*)d_in[4];
    const float* W1    = (const float*)d_in[5];
    const float* b1    = (const float*)d_in[6];
    const float* W2    = (const float*)d_in[7];
    const float* b2    = (const float*)d_in[8];
    float* out = (float*)d_out;

    float *S, *Vt, *G, *H, *Wt, *Dr, *Er;
    cudaGetSymbolAddress((void**)&S,  g_S);
    cudaGetSymbolAddress((void**)&Vt, g_Vt);
    cudaGetSymbolAddress((void**)&G,  g_G);
    cudaGetSymbolAddress((void**)&H,  g_H);
    cudaGetSymbolAddress((void**)&Wt, g_Wt);
    cudaGetSymbolAddress((void**)&Dr, g_Dr);
    cudaGetSymbolAddress((void**)&Er, g_Er);
    float* Wvt = Wt;
    float* W1t = Wt + (size_t)C_ * C_;
    float* W2t = Wt + 2 * (size_t)C_ * C_;

    const size_t NC = (size_t)N_ * C_;
    const size_t MC = (size_t)M_ * C_;
    const size_t NM = (size_t)N_ * M_;
    const size_t CM = (size_t)C_ * M_;

    const int n8 = (int)(NC * B_ / 8);
    dim3 tb(32, 8), tg(C_ / 32, C_ / 32);

    // Launch order chosen so the BIG gemm (EPI=1) is the 6th launch -> ncu
    // (-s 5 -c 1) profiles it next round.
    round_perm8<<<(n8 + 255) / 256, 256>>>((const float4*)dec, (float4*)Dr, n8);  // 1
    round_perm8<<<(n8 + 255) / 256, 256>>>((const float4*)enc, (float4*)Er, n8);  // 2
    transpose512<<<tg, tb>>>(Wv, Wvt);                                            // 3
    transpose512<<<tg, tb>>>(W1, W1t);                                            // 4
    transpose512<<<tg, tb>>>(W2, W2t);                                            // 5

    // S[b,n,m] = (dec[b,n,:] . enc[b,m,:]) * trans[b,n,m]   (6th: profiled)
    launch_gemm<1>(dim3(M_ / 128, N_ / 128, B_), Dr, Er, S, nullptr, trans, M_, C_, NC, MC, NM, NM);

    // Vt[b][c][m] = sum_k Wv[k,c]*enc[b,m,k] + bv[c]
    launch_gemm<0>(dim3(M_ / 128, C_ / 128, B_), Wvt, Er, Vt, bv, nullptr, M_, C_, 0, MC, CM, 0);

    // in-place masked softmax over m (permuted rows; writes tf32-rounded P)
    softmax_k<<<B_ * N_, 256>>>(S);

    // G[b,n,c] = dec[b,n,c] * (1 + tanh(sum_m P[b,n,m]*Vt[b][c][m]))
    launch_gemm<2>(dim3(C_ / 128, N_ / 128, B_), S, Vt, G, nullptr, dec, C_, M_, NM, CM, NC, NC);

    // H = relu(G @ W1 + b1)
    launch_gemm<3>(dim3(C_ / 128, (B_ * N_) / 128, 1), G, W1t, H, b1, nullptr, C_, C_, 0, 0, 0, 0);

    // out = H @ W2 + b2
    launch_gemm<4>(dim3(C_ / 128, (B_ * N_) / 128, 1), H, W2t, out, b2, nullptr, C_, C_, 0, 0, 0, 0);
}

// round 13
// speedup vs baseline: 2.1465x; 1.5969x over previous
#include <cuda_runtime.h>
#include <cuda_fp16.h>
#include <cstdint>
#include <math.h>

// Problem shape (fixed by the dataset)
constexpr int B_  = 8;
constexpr int N_  = 2048;
constexpr int M_  = 2048;
constexpr int C_  = 512;

// -------- scratch (device-global arrays: allocation-free rule) --------
__device__ float  g_S [(size_t)B_ * N_ * M_];   // scores (fp32, softmax input)
__device__ __half g_P [(size_t)B_ * N_ * M_];   // probabilities (fp16)
__device__ __half g_Vt[(size_t)B_ * C_ * M_];   // V^T per batch [C][M]
__device__ __half g_G [(size_t)B_ * N_ * C_];   // gated activations
__device__ __half g_H [(size_t)B_ * N_ * C_];   // MLP hidden
__device__ __half g_Wt[3 * C_ * C_];            // Wv^T, W1^T, W2^T
__device__ __half g_Dr[(size_t)B_ * N_ * C_];   // dec, fp16
__device__ __half g_Er[(size_t)B_ * M_ * C_];   // enc, fp16

__device__ __forceinline__ void cp16(void* smem, const void* gmem) {
    unsigned sa = (unsigned)__cvta_generic_to_shared(smem);
    asm volatile("cp.async.cg.shared.global [%0], [%1], 16;\n" :: "r"(sa), "l"(gmem));
}
#define CP_COMMIT() asm volatile("cp.async.commit_group;\n")
#define CP_WAIT2()  asm volatile("cp.async.wait_group 2;\n")

// ==================== prep kernels ====================
__global__ void to_half8(const float4* __restrict__ in, __half2* __restrict__ out, int n4) {
    int i = blockIdx.x * 256 + threadIdx.x;
    if (i < n4) {
        float4 v = in[i];
        out[2 * i]     = __floats2half2_rn(v.x, v.y);
        out[2 * i + 1] = __floats2half2_rn(v.z, v.w);
    }
}

__global__ void transpose512h(const float* __restrict__ in, __half* __restrict__ out) {
    __shared__ float tile[32][33];
    int x = blockIdx.x * 32 + threadIdx.x;
    int y = blockIdx.y * 32 + threadIdx.y;
#pragma unroll
    for (int i = 0; i < 32; i += 8)
        tile[threadIdx.y + i][threadIdx.x] = in[(size_t)(y + i) * C_ + x];
    __syncthreads();
    int x2 = blockIdx.y * 32 + threadIdx.x;
    int y2 = blockIdx.x * 32 + threadIdx.y;
#pragma unroll
    for (int i = 0; i < 32; i += 8)
        out[(size_t)(y2 + i) * C_ + x2] = __float2half_rn(tile[threadIdx.x][threadIdx.y + i]);
}

// ==================== fp16 NT GEMM (fp32 accumulate) ====================
// D[i,j] = sum_k A[i,k]*B[j,k].  CTA tile 128x128, kblock=32, 8 warps at 64x32,
// 4-stage cp.async, 2 CTAs/SM. Operands fp16, accum fp32 (m16n8k16).
// smem row = 32 fp16 = 64B = 4 chunks of 16B, chunk swizzle s(r)=(r>>1)&3
// -> conflict-free fragment LDS.32 AND conflict-free ldgsts writes.
// EPI: 0 = half(v+bias[row])            (Vt)
//      1 = v*extra (fp32 out)           (scores)
//      2 = half(extra*(1+tanh(v)))      (tanh-gate, extra = fp32 dec)
//      3 = half(relu(v+bias[col]))      (fc1)
//      4 = v+bias[col] (fp32 out)       (final)
#define MMA_F16(d, a, b)                                                       \
    asm volatile(                                                              \
        "mma.sync.aligned.m16n8k16.row.col.f32.f16.f16.f32 "                   \
        "{%0,%1,%2,%3}, {%4,%5,%6,%7}, {%8,%9}, {%0,%1,%2,%3};\n"              \
        : "+f"(d[0]), "+f"(d[1]), "+f"(d[2]), "+f"(d[3])                       \
        : "r"(a[0]), "r"(a[1]), "r"(a[2]), "r"(a[3]), "r"(b[0]), "r"(b[1]))

constexpr int STAGES      = 4;
constexpr int HALF_TILE_B = 128 * 32 * 2;              // 8 KB per operand tile
constexpr int STAGE_BYTES = 2 * HALF_TILE_B;           // 16 KB
constexpr int GEMM_SMEM   = STAGES * STAGE_BYTES;      // 64 KB

template <int EPI>
__global__ __launch_bounds__(256, 2)
void gemm_h(const __half* __restrict__ A, const __half* __restrict__ Bop,
            void* __restrict__ Dv, const float* __restrict__ bias,
            const float* __restrict__ extra,
            int Ncols, int K,
            size_t batA, size_t batB, size_t batD, size_t batE) {
    extern __shared__ char smem[];

    const int tid  = threadIdx.x;
    const int warp = tid >> 5, lane = tid & 31;
    const int wm = warp >> 2, wn = warp & 3;       // 2 x 4 warps, each 64x32
    const int g = lane >> 2, t = lane & 3;

    const __half* Ag = A   + (size_t)blockIdx.z * batA + (size_t)blockIdx.y * 128 * K;
    const __half* Bg = Bop + (size_t)blockIdx.z * batB + (size_t)blockIdx.x * 128 * K;

    // loader: thread -> row tid>>1, chunks (tid&1)*2 + {0,1} of both tiles
    const int lr = tid >> 1;
    const int lc = (tid & 1) * 2;
    const int lsw = (lr >> 1) & 3;

    auto issue = [&](int kb, int stg) {
        char* sA = smem + stg * STAGE_BYTES;
        char* sB = sA + HALF_TILE_B;
        const __half* ag = Ag + (size_t)lr * K + kb * 32;
        const __half* bg = Bg + (size_t)lr * K + kb * 32;
#pragma unroll
        for (int j = 0; j < 2; ++j) {
            const int c = lc + j;
            const int pc = (c ^ lsw) << 4;
            cp16(sA + lr * 64 + pc, ag + c * 8);
            cp16(sB + lr * 64 + pc, bg + c * 8);
        }
    };

    float acc[4][4][4];
#pragma unroll
    for (int a = 0; a < 4; ++a)
#pragma unroll
        for (int b = 0; b < 4; ++b)
#pragma unroll
            for (int r = 0; r < 4; ++r) acc[a][b][r] = 0.f;

    const int nkt = K >> 5;              // >= 16 always
    issue(0, 0); CP_COMMIT();
    issue(1, 1); CP_COMMIT();
    issue(2, 2); CP_COMMIT();

    // fragment byte offsets within a row: chunk (lc^s)<<4 plus granule t*4
    const int s = (g >> 1) & 3;
    int px[4];
#pragma unroll
    for (int c = 0; c < 4; ++c) px[c] = (((c ^ s) << 4) | (t << 2));

    for (int kb = 0; kb < nkt; ++kb) {
        CP_WAIT2();                      // stage kb landed
        __syncthreads();
        if (kb + 3 < nkt) issue(kb + 3, (kb + 3) & (STAGES - 1));
        CP_COMMIT();                     // keep group count uniform

        const char* sA = smem + (kb & (STAGES - 1)) * STAGE_BYTES;
        const char* sB = sA + HALF_TILE_B;

#pragma unroll
        for (int ks = 0; ks < 2; ++ks) {
            const int p0 = px[ks * 2], p1 = px[ks * 2 + 1];
            unsigned af[4][4], bf[4][2];
#pragma unroll
            for (int am = 0; am < 4; ++am) {
                const char* r0 = sA + (wm * 64 + am * 16 + g) * 64;
                af[am][0] = *(const unsigned*)(r0 + p0);
                af[am][1] = *(const unsigned*)(r0 + 512 + p0);   // +8 rows
                af[am][2] = *(const unsigned*)(r0 + p1);
                af[am][3] = *(const unsigned*)(r0 + 512 + p1);
            }
#pragma unroll
            for (int an = 0; an < 4; ++an) {
                const char* nb = sB + (wn * 32 + an * 8 + g) * 64;
                bf[an][0] = *(const unsigned*)(nb + p0);
                bf[an][1] = *(const unsigned*)(nb + p1);
            }
#pragma unroll
            for (int am = 0; am < 4; ++am)
#pragma unroll
                for (int an = 0; an < 4; ++an)
                    MMA_F16(acc[am][an], af[am], bf[an]);
        }
    }

    // -------- epilogue --------
    const int mbase = blockIdx.y * 128 + wm * 64;
    const int nbase = blockIdx.x * 128 + wn * 32;
    const float* Eb = (EPI == 1 || EPI == 2) ? extra + (size_t)blockIdx.z * batE : nullptr;

#pragma unroll
    for (int am = 0; am < 4; ++am) {
#pragma unroll
        for (int hh = 0; hh < 2; ++hh) {
            const int row = mbase + am * 16 + g + hh * 8;
            const float* erow = (EPI == 1 || EPI == 2)
                                ? Eb + (size_t)row * Ncols + nbase : nullptr;
            const float brow = (EPI == 0) ? bias[row] : 0.0f;
#pragma unroll
            for (int an = 0; an < 4; ++an) {
                float v0 = acc[am][an][hh * 2 + 0];
                float v1 = acc[am][an][hh * 2 + 1];
                const int ctru = an * 8 + t * 2;
                if constexpr (EPI == 0) {
                    __half* drow = (__half*)Dv + (size_t)blockIdx.z * batD
                                   + (size_t)row * Ncols + nbase;
                    *reinterpret_cast<__half2*>(drow + ctru) =
                        __floats2half2_rn(v0 + brow, v1 + brow);
                } else if constexpr (EPI == 1) {
                    float* drow = (float*)Dv + (size_t)blockIdx.z * batD
                                  + (size_t)row * Ncols + nbase;
                    float2 e = *reinterpret_cast<const float2*>(erow + ctru);
                    *reinterpret_cast<float2*>(drow + ctru) =
                        make_float2(v0 * e.x, v1 * e.y);
                } else if constexpr (EPI == 2) {
                    __half* drow = (__half*)Dv + (size_t)blockIdx.z * batD
                                   + (size_t)row * Ncols + nbase;
                    float2 e = *reinterpret_cast<const float2*>(erow + ctru);
                    *reinterpret_cast<__half2*>(drow + ctru) =
                        __floats2half2_rn(e.x * (1.0f + tanhf(v0)),
                                          e.y * (1.0f + tanhf(v1)));
                } else if constexpr (EPI == 3) {
                    __half* drow = (__half*)Dv + (size_t)blockIdx.z * batD
                                   + (size_t)row * Ncols + nbase;
                    const int c = nbase + ctru;
                    *reinterpret_cast<__half2*>(drow + ctru) =
                        __floats2half2_rn(fmaxf(v0 + bias[c], 0.0f),
                                          fmaxf(v1 + bias[c + 1], 0.0f));
                } else {
                    float* drow = (float*)Dv + (size_t)blockIdx.z * batD
                                  + (size_t)row * Ncols + nbase;
                    const int c = nbase + ctru;
                    *reinterpret_cast<float2*>(drow + ctru) =
                        make_float2(v0 + bias[c], v1 + bias[c + 1]);
                }
            }
        }
    }
}

// ==================== nonstandard masked softmax ====================
// Reads fp32 S row, writes fp16 P row. max over ALL entries; denom includes
// exp(0-max) for masked entries; entries exactly 0 stay 0.
__global__ __launch_bounds__(256)
void softmax_k(const float* __restrict__ S, __half* __restrict__ P) {
    __shared__ float red[8];
    const int tid = threadIdx.x;
    const float4* p4 = reinterpret_cast<const float4*>(S + (size_t)blockIdx.x * M_);
    __half2* o2 = reinterpret_cast<__half2*>(P + (size_t)blockIdx.x * M_);

    float mx = -3.402823466e38f;
    float4 v[2];
#pragma unroll
    for (int j = 0; j < 2; ++j) {
        v[j] = p4[tid + j * 256];
        mx = fmaxf(mx, fmaxf(fmaxf(v[j].x, v[j].y), fmaxf(v[j].z, v[j].w)));
    }
#pragma unroll
    for (int o = 16; o > 0; o >>= 1) mx = fmaxf(mx, __shfl_xor_sync(0xffffffffu, mx, o));
    if ((tid & 31) == 0) red[tid >> 5] = mx;
    __syncthreads();
    if (tid == 0) {
        float m = red[0];
#pragma unroll
        for (int j = 1; j < 8; ++j) m = fmaxf(m, red[j]);
        red[0] = m;
    }
    __syncthreads();
    mx = red[0];
    __syncthreads();

    float e[8];
    float s = 0.f;
#pragma unroll
    for (int j = 0; j < 2; ++j) {
        e[j * 4 + 0] = expf(v[j].x - mx);
        e[j * 4 + 1] = expf(v[j].y - mx);
        e[j * 4 + 2] = expf(v[j].z - mx);
        e[j * 4 + 3] = expf(v[j].w - mx);
        s += e[j * 4 + 0] + e[j * 4 + 1] + e[j * 4 + 2] + e[j * 4 + 3];
    }
#pragma unroll
    for (int o = 16; o > 0; o >>= 1) s += __shfl_xor_sync(0xffffffffu, s, o);
    if ((tid & 31) == 0) red[tid >> 5] = s;
    __syncthreads();
    if (tid == 0) {
        float tot = 0.f;
#pragma unroll
        for (int j = 0; j < 8; ++j) tot += red[j];
        red[0] = tot;
    }
    __syncthreads();
    const float inv = 1.0f / red[0];

#pragma unroll
    for (int j = 0; j < 2; ++j) {
        float w0 = (v[j].x != 0.0f) ? e[j * 4 + 0] * inv : 0.0f;
        float w1 = (v[j].y != 0.0f) ? e[j * 4 + 1] * inv : 0.0f;
        float w2 = (v[j].z != 0.0f) ? e[j * 4 + 2] * inv : 0.0f;
        float w3 = (v[j].w != 0.0f) ? e[j * 4 + 3] * inv : 0.0f;
        o2[(tid + j * 256) * 2 + 0] = __floats2half2_rn(w0, w1);
        o2[(tid + j * 256) * 2 + 1] = __floats2half2_rn(w2, w3);
    }
}

template <int EPI>
static void launch_gemm(dim3 grid, const __half* A, const __half* Bop, void* D,
                        const float* bias, const float* extra,
                        int Ncols, int K, size_t batA, size_t batB, size_t batD, size_t batE) {
    static bool attr_done = false;
    if (!attr_done) {
        cudaFuncSetAttribute(gemm_h<EPI>, cudaFuncAttributeMaxDynamicSharedMemorySize, GEMM_SMEM);
        attr_done = true;
    }
    gemm_h<EPI><<<grid, 256, GEMM_SMEM>>>(A, Bop, D, bias, extra, Ncols, K, batA, batB, batD, batE);
}

extern "C" void kernel_launch(void* const* d_in, const int* in_sizes, int n_in,
                              void* d_out, int out_size) {
    (void)in_sizes; (void)n_in; (void)out_size;
    const float* dec   = (const float*)d_in[0];
    const float* enc   = (const float*)d_in[1];
    const float* trans = (const float*)d_in[2];
    const float* Wv    = (const float*)d_in[3];
    const float* bv    = (const float*)d_in[4];
    const float* W1    = (const float*)d_in[5];
    const float* b1    = (const float*)d_in[6];
    const float* W2    = (const float*)d_in[7];
    const float* b2    = (const float*)d_in[8];
    float* out = (float*)d_out;

    float *S;
    __half *P, *Vt, *G, *H, *Wt, *Dr, *Er;
    cudaGetSymbolAddress((void**)&S,  g_S);
    cudaGetSymbolAddress((void**)&P,  g_P);
    cudaGetSymbolAddress((void**)&Vt, g_Vt);
    cudaGetSymbolAddress((void**)&G,  g_G);
    cudaGetSymbolAddress((void**)&H,  g_H);
    cudaGetSymbolAddress((void**)&Wt, g_Wt);
    cudaGetSymbolAddress((void**)&Dr, g_Dr);
    cudaGetSymbolAddress((void**)&Er, g_Er);
    __half* Wvt = Wt;
    __half* W1t = Wt + (size_t)C_ * C_;
    __half* W2t = Wt + 2 * (size_t)C_ * C_;

    const size_t NC = (size_t)N_ * C_;
    const size_t MC = (size_t)M_ * C_;
    const size_t NM = (size_t)N_ * M_;
    const size_t CM = (size_t)C_ * M_;

    const int n4 = (int)(NC * B_ / 4);
    dim3 tb(32, 8), tg(C_ / 32, C_ / 32);

    // Launch order keeps the BIG gemm (EPI=1) 6th -> ncu (-s 5 -c 1) profiles it.
    to_half8<<<(n4 + 255) / 256, 256>>>((const float4*)dec, (__half2*)Dr, n4);   // 1
    to_half8<<<(n4 + 255) / 256, 256>>>((const float4*)enc, (__half2*)Er, n4);   // 2
    transpose512h<<<tg, tb>>>(Wv, Wvt);                                          // 3
    transpose512h<<<tg, tb>>>(W1, W1t);                                          // 4
    transpose512h<<<tg, tb>>>(W2, W2t);                                          // 5

    // S[b,n,m] = (dec[b,n,:] . enc[b,m,:]) * trans[b,n,m]   (6th: profiled)
    launch_gemm<1>(dim3(M_ / 128, N_ / 128, B_), Dr, Er, S, nullptr, trans,
                   M_, C_, NC, MC, NM, NM);

    // Vt[b][c][m] = sum_k Wv[k,c]*enc[b,m,k] + bv[c]
    launch_gemm<0>(dim3(M_ / 128, C_ / 128, B_), Wvt, Er, Vt, bv, nullptr,
                   M_, C_, 0, MC, CM, 0);

    // masked softmax over m: fp32 S -> fp16 P
    softmax_k<<<B_ * N_, 256>>>(S, P);

    // G[b,n,c] = dec[b,n,c] * (1 + tanh(sum_m P[b,n,m]*Vt[b][c][m]))
    launch_gemm<2>(dim3(C_ / 128, N_ / 128, B_), P, Vt, G, nullptr, dec,
                   C_, M_, NM, CM, NC, NC);

    // H = relu(G @ W1 + b1)
    launch_gemm<3>(dim3(C_ / 128, (B_ * N_) / 128, 1), G, W1t, H, b1, nullptr,
                   C_, C_, 0, 0, 0, 0);

    // out = H @ W2 + b2
    launch_gemm<4>(dim3(C_ / 128, (B_ * N_) / 128, 1), H, W2t, out, b2, nullptr,
                   C_, C_, 0, 0, 0, 0);
}

// round 15
// speedup vs baseline: 2.3284x; 1.0848x over previous
#include <cuda_runtime.h>
#include <cuda_fp16.h>
#include <cstdint>
#include <math.h>

// Problem shape (fixed by the dataset)
constexpr int B_  = 8;
constexpr int N_  = 2048;
constexpr int M_  = 2048;
constexpr int C_  = 512;

// -------- scratch (device-global arrays: allocation-free rule) --------
__device__ float  g_S [(size_t)B_ * N_ * M_];   // scores (fp32, softmax input)
__device__ __half g_P [(size_t)B_ * N_ * M_];   // probabilities (fp16)
__device__ __half g_Vt[(size_t)B_ * C_ * M_];   // V^T per batch [C][M]
__device__ __half g_G [(size_t)B_ * N_ * C_];   // gated activations
__device__ __half g_H [(size_t)B_ * N_ * C_];   // MLP hidden
__device__ __half g_Wt[3 * C_ * C_];            // Wv^T, W1^T, W2^T
__device__ __half g_Dr[(size_t)B_ * N_ * C_];   // dec, fp16
__device__ __half g_Er[(size_t)B_ * M_ * C_];   // enc, fp16

__device__ __forceinline__ void cp16(uint32_t saddr, const void* gmem) {
    asm volatile("cp.async.cg.shared.global [%0], [%1], 16;\n" :: "r"(saddr), "l"(gmem));
}
#define CP_COMMIT() asm volatile("cp.async.commit_group;\n")
#define CP_WAIT1()  asm volatile("cp.async.wait_group 1;\n")

#define LDSM4(r, addr)                                                          \
    asm volatile("ldmatrix.sync.aligned.m8n8.x4.shared.b16 {%0,%1,%2,%3}, [%4];" \
                 : "=r"((r)[0]), "=r"((r)[1]), "=r"((r)[2]), "=r"((r)[3])       \
                 : "r"(addr))
#define LDSM2(r, addr)                                                          \
    asm volatile("ldmatrix.sync.aligned.m8n8.x2.shared.b16 {%0,%1}, [%2];"      \
                 : "=r"((r)[0]), "=r"((r)[1]) : "r"(addr))

// ==================== prep kernels ====================
// one launch converts BOTH dec and enc (blockIdx.y selects)
__global__ void to_half_all(const float4* __restrict__ a, __half2* __restrict__ oa,
                            const float4* __restrict__ b, __half2* __restrict__ ob, int n4) {
    int i = blockIdx.x * 256 + threadIdx.x;
    const float4* in = blockIdx.y ? b : a;
    __half2* out = blockIdx.y ? ob : oa;
    if (i < n4) {
        float4 v = in[i];
        out[2 * i]     = __floats2half2_rn(v.x, v.y);
        out[2 * i + 1] = __floats2half2_rn(v.z, v.w);
    }
}

__global__ void transpose512h(const float* __restrict__ in, __half* __restrict__ out) {
    __shared__ float tile[32][33];
    int x = blockIdx.x * 32 + threadIdx.x;
    int y = blockIdx.y * 32 + threadIdx.y;
#pragma unroll
    for (int i = 0; i < 32; i += 8)
        tile[threadIdx.y + i][threadIdx.x] = in[(size_t)(y + i) * C_ + x];
    __syncthreads();
    int x2 = blockIdx.y * 32 + threadIdx.x;
    int y2 = blockIdx.x * 32 + threadIdx.y;
#pragma unroll
    for (int i = 0; i < 32; i += 8)
        out[(size_t)(y2 + i) * C_ + x2] = __float2half_rn(tile[threadIdx.x][threadIdx.y + i]);
}

// ==================== fp16 NT GEMM (fp32 accumulate) ====================
// D[i,j] = sum_k A[i,k]*B[j,k].  CTA tile 128x128, k-chunk 64 per stage,
// 8 warps at 64x32, 3-stage cp.async, 2 CTAs/SM, ldmatrix operand fetch.
// smem tile row = 64 fp16 = 128B = 8 chunks of 16B; chunk swizzle c ^= (row&7).
// EPI: 0 = half(v+bias[row])            (Vt)
//      1 = v*extra (fp32 out)           (scores)
//      2 = half(extra*(1+tanh(v)))      (tanh-gate, extra = fp32 dec)
//      3 = half(relu(v+bias[col]))      (fc1)
//      4 = v+bias[col] (fp32 out)       (final)
#define MMA_F16(d, a, b)                                                       \
    asm volatile(                                                              \
        "mma.sync.aligned.m16n8k16.row.col.f32.f16.f16.f32 "                   \
        "{%0,%1,%2,%3}, {%4,%5,%6,%7}, {%8,%9}, {%0,%1,%2,%3};\n"              \
        : "+f"(d[0]), "+f"(d[1]), "+f"(d[2]), "+f"(d[3])                       \
        : "r"(a[0]), "r"(a[1]), "r"(a[2]), "r"(a[3]), "r"(b[0]), "r"(b[1]))

constexpr int STAGES      = 3;
constexpr int TILE_BYTES  = 128 * 64 * 2;              // 16 KB per operand tile
constexpr int STAGE_BYTES = 2 * TILE_BYTES;            // 32 KB
constexpr int GEMM_SMEM   = STAGES * STAGE_BYTES;      // 96 KB

template <int EPI>
__global__ __launch_bounds__(256, 2)
void gemm_h(const __half* __restrict__ A, const __half* __restrict__ Bop,
            void* __restrict__ Dv, const float* __restrict__ bias,
            const float* __restrict__ extra,
            int Ncols, int K,
            size_t batA, size_t batB, size_t batD, size_t batE) {
    extern __shared__ char smem[];
    const uint32_t su = (uint32_t)__cvta_generic_to_shared(smem);

    const int tid  = threadIdx.x;
    const int warp = tid >> 5, lane = tid & 31;
    const int wm = warp >> 2, wn = warp & 3;       // 2 x 4 warps, each 64x32
    const int g = lane >> 2, t = lane & 3;

    const __half* Ag = A   + (size_t)blockIdx.z * batA + (size_t)blockIdx.y * 128 * K;
    const __half* Bg = Bop + (size_t)blockIdx.z * batB + (size_t)blockIdx.x * 128 * K;

    // loader: thread -> row tid>>1 (0..127), chunks (tid&1)*4 + j (j=0..3)
    const int lr  = tid >> 1;
    const int lcb = (tid & 1) * 4;
    const int lsw = lr & 7;

    auto issue = [&](int kt, int stg) {
        const uint32_t sA = su + stg * STAGE_BYTES;
        const uint32_t sB = sA + TILE_BYTES;
        const __half* ag = Ag + (size_t)lr * K + kt * 64;
        const __half* bg = Bg + (size_t)lr * K + kt * 64;
#pragma unroll
        for (int j = 0; j < 4; ++j) {
            const int c = lcb + j;
            const uint32_t pc = (uint32_t)((c ^ lsw) << 4) + lr * 128;
            cp16(sA + pc, ag + c * 8);
            cp16(sB + pc, bg + c * 8);
        }
    };

    // ldmatrix per-lane constants
    const int lm  = lane & 7;
    const int rA  = lm + ((lane >> 3) & 1) * 8;     // row-within-16 for A x4
    const int hiA = (lane >> 4) & 1;                // chunk half for A x4
    const int hiB = (lane >> 3) & 1;                // chunk half for B x2

    float acc[4][4][4];
#pragma unroll
    for (int a = 0; a < 4; ++a)
#pragma unroll
        for (int b = 0; b < 4; ++b)
#pragma unroll
            for (int r = 0; r < 4; ++r) acc[a][b][r] = 0.f;

    const int nkt = K >> 6;              // >= 8 always
    issue(0, 0); CP_COMMIT();
    issue(1, 1); CP_COMMIT();

    for (int kt = 0; kt < nkt; ++kt) {
        CP_WAIT1();                      // stage kt landed
        __syncthreads();
        if (kt + 2 < nkt) issue(kt + 2, (kt + 2) % STAGES);
        CP_COMMIT();                     // keep group count uniform

        const uint32_t sA = su + (kt % STAGES) * STAGE_BYTES;
        const uint32_t sB = sA + TILE_BYTES;
        uint32_t aBase[4], bBase[4];
#pragma unroll
        for (int am = 0; am < 4; ++am)
            aBase[am] = sA + (wm * 64 + am * 16 + rA) * 128;
#pragma unroll
        for (int an = 0; an < 4; ++an)
            bBase[an] = sB + (wn * 32 + an * 8 + lm) * 128;

#pragma unroll
        for (int ks = 0; ks < 4; ++ks) {
            const uint32_t cA = (uint32_t)(((2 * ks + hiA) ^ lm) << 4);
            const uint32_t cB = (uint32_t)(((2 * ks + hiB) ^ lm) << 4);
            unsigned af[4][4], bf[4][2];
#pragma unroll
            for (int am = 0; am < 4; ++am) LDSM4(af[am], aBase[am] + cA);
#pragma unroll
            for (int an = 0; an < 4; ++an) LDSM2(bf[an], bBase[an] + cB);
#pragma unroll
            for (int am = 0; am < 4; ++am)
#pragma unroll
                for (int an = 0; an < 4; ++an)
                    MMA_F16(acc[am][an], af[am], bf[an]);
        }
    }

    // -------- epilogue --------
    const int mbase = blockIdx.y * 128 + wm * 64;
    const int nbase = blockIdx.x * 128 + wn * 32;
    const float* Eb = (EPI == 1 || EPI == 2) ? extra + (size_t)blockIdx.z * batE : nullptr;

#pragma unroll
    for (int am = 0; am < 4; ++am) {
#pragma unroll
        for (int hh = 0; hh < 2; ++hh) {
            const int row = mbase + am * 16 + g + hh * 8;
            const float* erow = (EPI == 1 || EPI == 2)
                                ? Eb + (size_t)row * Ncols + nbase : nullptr;
            const float brow = (EPI == 0) ? bias[row] : 0.0f;
#pragma unroll
            for (int an = 0; an < 4; ++an) {
                float v0 = acc[am][an][hh * 2 + 0];
                float v1 = acc[am][an][hh * 2 + 1];
                const int ctru = an * 8 + t * 2;
                if constexpr (EPI == 0) {
                    __half* drow = (__half*)Dv + (size_t)blockIdx.z * batD
                                   + (size_t)row * Ncols + nbase;
                    *reinterpret_cast<__half2*>(drow + ctru) =
                        __floats2half2_rn(v0 + brow, v1 + brow);
                } else if constexpr (EPI == 1) {
                    float* drow = (float*)Dv + (size_t)blockIdx.z * batD
                                  + (size_t)row * Ncols + nbase;
                    float2 e = *reinterpret_cast<const float2*>(erow + ctru);
                    *reinterpret_cast<float2*>(drow + ctru) =
                        make_float2(v0 * e.x, v1 * e.y);
                } else if constexpr (EPI == 2) {
                    __half* drow = (__half*)Dv + (size_t)blockIdx.z * batD
                                   + (size_t)row * Ncols + nbase;
                    float2 e = *reinterpret_cast<const float2*>(erow + ctru);
                    *reinterpret_cast<__half2*>(drow + ctru) =
                        __floats2half2_rn(e.x * (1.0f + tanhf(v0)),
                                          e.y * (1.0f + tanhf(v1)));
                } else if constexpr (EPI == 3) {
                    __half* drow = (__half*)Dv + (size_t)blockIdx.z * batD
                                   + (size_t)row * Ncols + nbase;
                    const int c = nbase + ctru;
                    *reinterpret_cast<__half2*>(drow + ctru) =
                        __floats2half2_rn(fmaxf(v0 + bias[c], 0.0f),
                                          fmaxf(v1 + bias[c + 1], 0.0f));
                } else {
                    float* drow = (float*)Dv + (size_t)blockIdx.z * batD
                                  + (size_t)row * Ncols + nbase;
                    const int c = nbase + ctru;
                    *reinterpret_cast<float2*>(drow + ctru) =
                        make_float2(v0 + bias[c], v1 + bias[c + 1]);
                }
            }
        }
    }
}

// ==================== nonstandard masked softmax ====================
// Reads fp32 S row, writes fp16 P row. max over ALL entries; denom includes
// exp(0-max) for masked entries; entries exactly 0 stay 0.
__global__ __launch_bounds__(256)
void softmax_k(const float* __restrict__ S, __half* __restrict__ P) {
    __shared__ float red[8];
    const int tid = threadIdx.x;
    const float4* p4 = reinterpret_cast<const float4*>(S + (size_t)blockIdx.x * M_);
    __half2* o2 = reinterpret_cast<__half2*>(P + (size_t)blockIdx.x * M_);

    float mx = -3.402823466e38f;
    float4 v[2];
#pragma unroll
    for (int j = 0; j < 2; ++j) {
        v[j] = p4[tid + j * 256];
        mx = fmaxf(mx, fmaxf(fmaxf(v[j].x, v[j].y), fmaxf(v[j].z, v[j].w)));
    }
#pragma unroll
    for (int o = 16; o > 0; o >>= 1) mx = fmaxf(mx, __shfl_xor_sync(0xffffffffu, mx, o));
    if ((tid & 31) == 0) red[tid >> 5] = mx;
    __syncthreads();
    if (tid == 0) {
        float m = red[0];
#pragma unroll
        for (int j = 1; j < 8; ++j) m = fmaxf(m, red[j]);
        red[0] = m;
    }
    __syncthreads();
    mx = red[0];
    __syncthreads();

    float e[8];
    float s = 0.f;
#pragma unroll
    for (int j = 0; j < 2; ++j) {
        e[j * 4 + 0] = __expf(v[j].x - mx);
        e[j * 4 + 1] = __expf(v[j].y - mx);
        e[j * 4 + 2] = __expf(v[j].z - mx);
        e[j * 4 + 3] = __expf(v[j].w - mx);
        s += e[j * 4 + 0] + e[j * 4 + 1] + e[j * 4 + 2] + e[j * 4 + 3];
    }
#pragma unroll
    for (int o = 16; o > 0; o >>= 1) s += __shfl_xor_sync(0xffffffffu, s, o);
    if ((tid & 31) == 0) red[tid >> 5] = s;
    __syncthreads();
    if (tid == 0) {
        float tot = 0.f;
#pragma unroll
        for (int j = 0; j < 8; ++j) tot += red[j];
        red[0] = tot;
    }
    __syncthreads();
    const float inv = 1.0f / red[0];

#pragma unroll
    for (int j = 0; j < 2; ++j) {
        float w0 = (v[j].x != 0.0f) ? e[j * 4 + 0] * inv : 0.0f;
        float w1 = (v[j].y != 0.0f) ? e[j * 4 + 1] * inv : 0.0f;
        float w2 = (v[j].z != 0.0f) ? e[j * 4 + 2] * inv : 0.0f;
        float w3 = (v[j].w != 0.0f) ? e[j * 4 + 3] * inv : 0.0f;
        o2[(tid + j * 256) * 2 + 0] = __floats2half2_rn(w0, w1);
        o2[(tid + j * 256) * 2 + 1] = __floats2half2_rn(w2, w3);
    }
}

template <int EPI>
static void launch_gemm(dim3 grid, const __half* A, const __half* Bop, void* D,
                        const float* bias, const float* extra,
                        int Ncols, int K, size_t batA, size_t batB, size_t batD, size_t batE) {
    static bool attr_done = false;
    if (!attr_done) {
        cudaFuncSetAttribute(gemm_h<EPI>, cudaFuncAttributeMaxDynamicSharedMemorySize, GEMM_SMEM);
        attr_done = true;
    }
    gemm_h<EPI><<<grid, 256, GEMM_SMEM>>>(A, Bop, D, bias, extra, Ncols, K, batA, batB, batD, batE);
}

extern "C" void kernel_launch(void* const* d_in, const int* in_sizes, int n_in,
                              void* d_out, int out_size) {
    (void)in_sizes; (void)n_in; (void)out_size;
    const float* dec   = (const float*)d_in[0];
    const float* enc   = (const float*)d_in[1];
    const float* trans = (const float*)d_in[2];
    const float* Wv    = (const float*)d_in[3];
    const float* bv    = (const float*)d_in[4];
    const float* W1    = (const float*)d_in[5];
    const float* b1    = (const float*)d_in[6];
    const float* W2    = (const float*)d_in[7];
    const float* b2    = (const float*)d_in[8];
    float* out = (float*)d_out;

    float *S;
    __half *P, *Vt, *G, *H, *Wt, *Dr, *Er;
    cudaGetSymbolAddress((void**)&S,  g_S);
    cudaGetSymbolAddress((void**)&P,  g_P);
    cudaGetSymbolAddress((void**)&Vt, g_Vt);
    cudaGetSymbolAddress((void**)&G,  g_G);
    cudaGetSymbolAddress((void**)&H,  g_H);
    cudaGetSymbolAddress((void**)&Wt, g_Wt);
    cudaGetSymbolAddress((void**)&Dr, g_Dr);
    cudaGetSymbolAddress((void**)&Er, g_Er);
    __half* Wvt = Wt;
    __half* W1t = Wt + (size_t)C_ * C_;
    __half* W2t = Wt + 2 * (size_t)C_ * C_;

    const size_t NC = (size_t)N_ * C_;
    const size_t MC = (size_t)M_ * C_;
    const size_t NM = (size_t)N_ * M_;
    const size_t CM = (size_t)C_ * M_;

    const int n4 = (int)(NC * B_ / 4);
    dim3 tb(32, 8), tg(C_ / 32, C_ / 32);

    // Launch order: 4 launches before the BIG gemm (EPI=1) so ncu (-s 5 -c 1,
    // +1 internal launch) captures gemm<1>.
    to_half_all<<<dim3((n4 + 255) / 256, 2), 256>>>(
        (const float4*)dec, (__half2*)Dr, (const float4*)enc, (__half2*)Er, n4); // 1
    transpose512h<<<tg, tb>>>(Wv, Wvt);                                          // 2
    transpose512h<<<tg, tb>>>(W1, W1t);                                          // 3
    transpose512h<<<tg, tb>>>(W2, W2t);                                          // 4

    // S[b,n,m] = (dec[b,n,:] . enc[b,m,:]) * trans[b,n,m]   (5th: profiled)
    launch_gemm<1>(dim3(M_ / 128, N_ / 128, B_), Dr, Er, S, nullptr, trans,
                   M_, C_, NC, MC, NM, NM);

    // Vt[b][c][m] = sum_k Wv[k,c]*enc[b,m,k] + bv[c]
    launch_gemm<0>(dim3(M_ / 128, C_ / 128, B_), Wvt, Er, Vt, bv, nullptr,
                   M_, C_, 0, MC, CM, 0);

    // masked softmax over m: fp32 S -> fp16 P
    softmax_k<<<B_ * N_, 256>>>(S, P);

    // G[b,n,c] = dec[b,n,c] * (1 + tanh(sum_m P[b,n,m]*Vt[b][c][m]))
    launch_gemm<2>(dim3(C_ / 128, N_ / 128, B_), P, Vt, G, nullptr, dec,
                   C_, M_, NM, CM, NC, NC);

    // H = relu(G @ W1 + b1)
    launch_gemm<3>(dim3(C_ / 128, (B_ * N_) / 128, 1), G, W1t, H, b1, nullptr,
                   C_, C_, 0, 0, 0, 0);

    // out = H @ W2 + b2
    launch_gemm<4>(dim3(C_ / 128, (B_ * N_) / 128, 1), H, W2t, out, b2, nullptr,
                   C_, C_, 0, 0, 0, 0);
}